// round 3
// baseline (speedup 1.0000x reference)
#include <cuda_runtime.h>
#include <cstdint>

#define BATCH 16
#define CDIM 256
#define NPIX 10000
#define KDET 100
#define KREC 25
#define GTOK 16
#define TPAD 18
#define PPARTS 8
#define DET_BLOCKS ((BATCH*KDET)/GTOK)   /* 100 */
#define REC_BLOCKS ((BATCH*KREC)/GTOK)   /* 25  */

// ---------------- scratch (static device globals) ----------------
__device__ float g_pos[CDIM * NPIX];          // resized positional embedding [C, N]
__device__ float g_ppp[PPARTS * 6 * NPIX];    // partial pos projections
__device__ float g_pp[6 * NPIX];              // pos projections onto Wc(2)+Wb(4)
__device__ float g_conf[BATCH * NPIX];        // margin l1-l0
__device__ int   g_idx[BATCH * KDET];         // top-100 indices per batch

// ---------------- f32x2 packed helpers ----------------
__device__ __forceinline__ unsigned long long pk2(float a, float b) {
    unsigned long long r;
    asm("mov.b64 %0, {%1,%2};" : "=l"(r) : "f"(a), "f"(b));
    return r;
}
__device__ __forceinline__ void upk2(unsigned long long v, float& a, float& b) {
    asm("mov.b64 {%0,%1}, %2;" : "=f"(a), "=f"(b) : "l"(v));
}
__device__ __forceinline__ unsigned long long fma2(unsigned long long a, unsigned long long b, unsigned long long c) {
    unsigned long long d;
    asm("fma.rn.f32x2 %0, %1, %2, %3;" : "=l"(d) : "l"(a), "l"(b), "l"(c));
    return d;
}

// ---------------- A1: bilinear resize 50x50 -> 100x100 ----------------
__global__ void pos_resize_kernel(const float* __restrict__ pe) {
    int i = blockIdx.x * blockDim.x + threadIdx.x;
    if (i >= CDIM * NPIX) return;
    int c = i / NPIX, pix = i % NPIX;
    int y = pix / 100, x = pix % 100;
    float sy = (y + 0.5f) * 0.5f - 0.5f; sy = fminf(fmaxf(sy, 0.f), 49.f);
    int y0 = (int)floorf(sy); int y1 = min(y0 + 1, 49); float ty = sy - (float)y0;
    float sx = (x + 0.5f) * 0.5f - 0.5f; sx = fminf(fmaxf(sx, 0.f), 49.f);
    int x0 = (int)floorf(sx); int x1 = min(x0 + 1, 49); float tx = sx - (float)x0;
    const float* p = pe + c * 2500;
    float v00 = p[y0 * 50 + x0], v01 = p[y0 * 50 + x1];
    float v10 = p[y1 * 50 + x0], v11 = p[y1 * 50 + x1];
    float r0 = v00 * (1.f - ty) + v10 * ty;
    float r1 = v01 * (1.f - ty) + v11 * ty;
    g_pos[i] = r0 * (1.f - tx) + r1 * tx;
}

// ---------------- A2: pos projection, C split 8 ways ----------------
__global__ void pos_proj_part_kernel(const float* __restrict__ Wc, const float* __restrict__ Wb) {
    __shared__ float ws[6 * 256];
    int tid = threadIdx.x;
    for (int i = tid; i < 2 * 256; i += blockDim.x) ws[i] = Wc[i];
    for (int i = tid; i < 4 * 256; i += blockDim.x) ws[512 + i] = Wb[i];
    __syncthreads();
    int id = blockIdx.x * blockDim.x + tid;
    if (id >= PPARTS * (NPIX / 2)) return;
    int part = id / (NPIX / 2);
    int n2 = (id % (NPIX / 2)) * 2;
    int c0 = part * 32;
    float2 a[6];
    #pragma unroll
    for (int w = 0; w < 6; w++) a[w] = make_float2(0.f, 0.f);
    #pragma unroll 8
    for (int i = 0; i < 32; i++) {
        int c = c0 + i;
        float2 p = *reinterpret_cast<const float2*>(g_pos + (size_t)c * NPIX + n2);
        #pragma unroll
        for (int w = 0; w < 6; w++) {
            float wv = ws[w * 256 + c];
            a[w].x += p.x * wv; a[w].y += p.y * wv;
        }
    }
    #pragma unroll
    for (int w = 0; w < 6; w++)
        *reinterpret_cast<float2*>(g_ppp + ((size_t)part * 6 + w) * NPIX + n2) = a[w];
}

__global__ void pos_proj_reduce_kernel() {
    int id = blockIdx.x * blockDim.x + threadIdx.x;
    if (id >= 6 * (NPIX / 4)) return;
    int w = id / (NPIX / 4);
    int n4 = (id % (NPIX / 4)) * 4;
    float4 s = make_float4(0.f, 0.f, 0.f, 0.f);
    #pragma unroll
    for (int p = 0; p < PPARTS; p++) {
        float4 v = *reinterpret_cast<const float4*>(g_ppp + ((size_t)p * 6 + w) * NPIX + n4);
        s.x += v.x; s.y += v.y; s.z += v.z; s.w += v.w;
    }
    *reinterpret_cast<float4*>(g_pp + (size_t)w * NPIX + n4) = s;
}

// ---------------- B: stream x once (float4), emit cls/bbox/margin ----------------
__global__ void __launch_bounds__(320) main_pass_kernel(
        const float* __restrict__ x,
        const float* __restrict__ bc, const float* __restrict__ bb,
        const float* __restrict__ Wc, const float* __restrict__ Wb,
        float* __restrict__ out_cls, float* __restrict__ out_bb) {
    __shared__ float ws[6 * 256];
    int tid = threadIdx.x;
    for (int i = tid; i < 2 * 256; i += blockDim.x) ws[i] = Wc[i];
    for (int i = tid; i < 4 * 256; i += blockDim.x) ws[512 + i] = Wb[i];
    __syncthreads();
    int id = blockIdx.x * blockDim.x + tid;
    if (id >= BATCH * (NPIX / 4)) return;
    int b = id / (NPIX / 4);
    int n4 = (id % (NPIX / 4)) * 4;
    const float4* xp = reinterpret_cast<const float4*>(x + (size_t)b * CDIM * NPIX + n4);
    float4 a0 = make_float4(0,0,0,0), a1 = a0, a2 = a0, a3 = a0, a4 = a0, a5 = a0;
    #pragma unroll 8
    for (int c = 0; c < 256; c++) {
        float4 v = __ldg(&xp[(size_t)c * (NPIX / 4)]);
        float w0 = ws[c], w1 = ws[256 + c], w2 = ws[512 + c];
        float w3 = ws[768 + c], w4 = ws[1024 + c], w5 = ws[1280 + c];
        a0.x += v.x * w0; a0.y += v.y * w0; a0.z += v.z * w0; a0.w += v.w * w0;
        a1.x += v.x * w1; a1.y += v.y * w1; a1.z += v.z * w1; a1.w += v.w * w1;
        a2.x += v.x * w2; a2.y += v.y * w2; a2.z += v.z * w2; a2.w += v.w * w2;
        a3.x += v.x * w3; a3.y += v.y * w3; a3.z += v.z * w3; a3.w += v.w * w3;
        a4.x += v.x * w4; a4.y += v.y * w4; a4.z += v.z * w4; a4.w += v.w * w4;
        a5.x += v.x * w5; a5.y += v.y * w5; a5.z += v.z * w5; a5.w += v.w * w5;
    }
    float4 p0 = *reinterpret_cast<const float4*>(g_pp + 0 * NPIX + n4);
    float4 p1 = *reinterpret_cast<const float4*>(g_pp + 1 * NPIX + n4);
    float4 p2 = *reinterpret_cast<const float4*>(g_pp + 2 * NPIX + n4);
    float4 p3 = *reinterpret_cast<const float4*>(g_pp + 3 * NPIX + n4);
    float4 p4 = *reinterpret_cast<const float4*>(g_pp + 4 * NPIX + n4);
    float4 p5 = *reinterpret_cast<const float4*>(g_pp + 5 * NPIX + n4);
    float bc0 = bc[0], bc1 = bc[1];
    float bb0 = bb[0], bb1 = bb[1], bb2 = bb[2], bb3 = bb[3];
    float4 l0 = make_float4(a0.x+p0.x+bc0, a0.y+p0.y+bc0, a0.z+p0.z+bc0, a0.w+p0.w+bc0);
    float4 l1 = make_float4(a1.x+p1.x+bc1, a1.y+p1.y+bc1, a1.z+p1.z+bc1, a1.w+p1.w+bc1);
    size_t co = ((size_t)b * NPIX + n4) * 2;
    *reinterpret_cast<float4*>(out_cls + co)     = make_float4(l0.x, l1.x, l0.y, l1.y);
    *reinterpret_cast<float4*>(out_cls + co + 4) = make_float4(l0.z, l1.z, l0.w, l1.w);
    size_t bo = ((size_t)b * NPIX + n4) * 4;
    *reinterpret_cast<float4*>(out_bb + bo)      = make_float4(a2.x+p2.x+bb0, a3.x+p3.x+bb1, a4.x+p4.x+bb2, a5.x+p5.x+bb3);
    *reinterpret_cast<float4*>(out_bb + bo + 4)  = make_float4(a2.y+p2.y+bb0, a3.y+p3.y+bb1, a4.y+p4.y+bb2, a5.y+p5.y+bb3);
    *reinterpret_cast<float4*>(out_bb + bo + 8)  = make_float4(a2.z+p2.z+bb0, a3.z+p3.z+bb1, a4.z+p4.z+bb2, a5.z+p5.z+bb3);
    *reinterpret_cast<float4*>(out_bb + bo + 12) = make_float4(a2.w+p2.w+bb0, a3.w+p3.w+bb1, a4.w+p4.w+bb2, a5.w+p5.w+bb3);
    *reinterpret_cast<float4*>(g_conf + (size_t)b * NPIX + n4) =
        make_float4(l1.x - l0.x, l1.y - l0.y, l1.z - l0.z, l1.w - l0.w);
}

// ---------------- C: exact per-batch top-100 (value desc, index asc) ----------------
// dynamic smem layout: cand[256] ull @0 | keys[NPIX] u32 @2048 | hist[2048] u32 @42048 | tot[257] u32 @50240
#define TK_SMEM (50240 + 260 * 4)
__global__ void __launch_bounds__(1024) topk_kernel() {
    extern __shared__ char sm[];
    unsigned long long* cand = reinterpret_cast<unsigned long long*>(sm);
    unsigned* keys = reinterpret_cast<unsigned*>(sm + 2048);
    unsigned* histv = reinterpret_cast<unsigned*>(sm + 42048);
    unsigned* tot = reinterpret_cast<unsigned*>(sm + 50240);
    __shared__ unsigned s_prefix;
    __shared__ int s_kk, s_cnt;
    int b = blockIdx.x, tid = threadIdx.x;

    for (int i = tid; i < NPIX; i += 1024) {
        unsigned u = __float_as_uint(g_conf[b * NPIX + i]);
        keys[i] = (u & 0x80000000u) ? ~u : (u | 0x80000000u);
    }
    if (tid == 0) { s_prefix = 0u; s_kk = KDET; s_cnt = 0; }
    __syncthreads();

    #pragma unroll
    for (int pass = 0; pass < 4; pass++) {
        int shift = 24 - 8 * pass;
        unsigned himask = (pass == 0) ? 0u : (0xFFFFFFFFu << (shift + 8));
        for (int i = tid; i < 2048; i += 1024) histv[i] = 0;
        __syncthreads();
        unsigned prefix = s_prefix;
        int kk = s_kk;
        unsigned* myh = histv + ((tid >> 5) & 7) * 256;
        for (int i = tid; i < NPIX; i += 1024) {
            unsigned u = keys[i];
            if (((u ^ prefix) & himask) == 0) atomicAdd(&myh[(u >> shift) & 255], 1u);
        }
        __syncthreads();
        if (tid < 256) {
            unsigned s = 0;
            #pragma unroll
            for (int cp = 0; cp < 8; cp++) s += histv[cp * 256 + tid];
            tot[tid] = s;
        }
        __syncthreads();
        // parallel suffix scan over 256 bins
        #pragma unroll
        for (int step = 1; step < 256; step <<= 1) {
            unsigned v = 0;
            if (tid < 256) v = tot[tid] + ((tid + step < 256) ? tot[tid + step] : 0u);
            __syncthreads();
            if (tid < 256) tot[tid] = v;
            __syncthreads();
        }
        if (tid < 256) {
            unsigned Sb = tot[tid];
            unsigned Sb1 = (tid < 255) ? tot[tid + 1] : 0u;
            if (Sb >= (unsigned)kk && Sb1 < (unsigned)kk) {
                s_prefix = prefix | ((unsigned)tid << shift);
                s_kk = kk - (int)Sb1;
            }
        }
        __syncthreads();
    }
    unsigned T = s_prefix;

    // collect candidates >= threshold; pack (key, ~idx)
    for (int i = tid; i < NPIX; i += 1024) {
        unsigned u = keys[i];
        if (u >= T) {
            int p = atomicAdd(&s_cnt, 1);
            if (p < 256)
                cand[p] = ((unsigned long long)u << 32) | (unsigned)(~(unsigned)i);
        }
    }
    __syncthreads();
    int cnt = min(s_cnt, 256);
    for (int i = cnt + tid; i < 256; i += 1024) cand[i] = 0ull;
    __syncthreads();

    // bitonic sort 256 descending => value desc, index asc on ties
    for (int ksz = 2; ksz <= 256; ksz <<= 1) {
        for (int j = ksz >> 1; j > 0; j >>= 1) {
            if (tid < 256) {
                int l = tid ^ j;
                if (l > tid) {
                    unsigned long long a = cand[tid], c2 = cand[l];
                    bool dirDesc = ((tid & ksz) == 0);
                    if ((a < c2) == dirDesc) { cand[tid] = c2; cand[l] = a; }
                }
            }
            __syncthreads();
        }
    }
    if (tid < KDET)
        g_idx[b * KDET + tid] = (int)(~((unsigned)(cand[tid] & 0xFFFFFFFFull)));
}

// ---------------- MLP: packed f32x2, token pairs, k-major activations ----------------
// shared layout (floats): bufA [256][TPAD] @0 | bufB [256][TPAD] @256*TPAD | Wt2 [32][514] @2*256*TPAD
#define MLP_SMEM ((2 * 256 * TPAD + 32 * 514) * 4)

__device__ __forceinline__ void run_layer2(const float* __restrict__ Wg, float bj,
                                           const float* __restrict__ bufIn,
                                           float* __restrict__ Wt2,
                                           unsigned long long acc[8]) {
    int tid = threadIdx.x;
    unsigned long long binit = pk2(bj, bj);
    #pragma unroll
    for (int p = 0; p < 8; p++) acc[p] = binit;
    for (int kc = 0; kc < 256; kc += 32) {
        // stage duplicated transposed weights: Wt2[i][2j .. 2j+1] = (W[j][kc+i], W[j][kc+i])
        #pragma unroll
        for (int r = 0; r < 8; r++) {
            int e = (r * 256 + tid) * 4;
            int j2 = e >> 5, i = e & 31;
            float4 w4 = *reinterpret_cast<const float4*>(Wg + j2 * 256 + kc + i);
            *reinterpret_cast<unsigned long long*>(&Wt2[(i + 0) * 514 + 2 * j2]) = pk2(w4.x, w4.x);
            *reinterpret_cast<unsigned long long*>(&Wt2[(i + 1) * 514 + 2 * j2]) = pk2(w4.y, w4.y);
            *reinterpret_cast<unsigned long long*>(&Wt2[(i + 2) * 514 + 2 * j2]) = pk2(w4.z, w4.z);
            *reinterpret_cast<unsigned long long*>(&Wt2[(i + 3) * 514 + 2 * j2]) = pk2(w4.w, w4.w);
        }
        __syncthreads();
        #pragma unroll 8
        for (int k = 0; k < 32; k++) {
            unsigned long long wd = *reinterpret_cast<const unsigned long long*>(&Wt2[k * 514 + 2 * tid]);
            const unsigned long long* tv =
                reinterpret_cast<const unsigned long long*>(&bufIn[(kc + k) * TPAD]);
            #pragma unroll
            for (int p = 0; p < 8; p++) acc[p] = fma2(tv[p], wd, acc[p]);
        }
        __syncthreads();
    }
}

__global__ void __launch_bounds__(256) mlp_kernel(
    const float* __restrict__ x,
    const float* __restrict__ dW1, const float* __restrict__ db1,
    const float* __restrict__ dW2, const float* __restrict__ db2,
    const float* __restrict__ dW3, const float* __restrict__ db3,
    const float* __restrict__ rW1, const float* __restrict__ rb1,
    const float* __restrict__ rW2, const float* __restrict__ rb2,
    const float* __restrict__ rW3, const float* __restrict__ rb3,
    const float* __restrict__ det_q, const float* __restrict__ rec_q,
    float* __restrict__ out_det, float* __restrict__ out_rec) {
    extern __shared__ float sh[];
    float* bufA = sh;
    float* bufB = sh + 256 * TPAD;
    float* Wt2  = sh + 2 * 256 * TPAD;
    int tid = threadIdx.x;
    bool isDet = blockIdx.x < DET_BLOCKS;
    int blk = isDet ? blockIdx.x : (blockIdx.x - DET_BLOCKS);
    int kq = isDet ? KDET : KREC;

    // gather feat rows (k-major layout: bufA[c][t])
    #pragma unroll 4
    for (int t = 0; t < GTOK; t++) {
        int g = blk * GTOK + t;
        int b = g / kq, qi = g % kq;
        int idx = g_idx[b * KDET + qi];
        float v = __ldg(x + ((size_t)(b * CDIM + tid)) * NPIX + idx) + g_pos[(size_t)tid * NPIX + idx];
        bufA[tid * TPAD + t] = v;
    }
    __syncthreads();

    const float* W1 = isDet ? dW1 : rW1; const float* b1 = isDet ? db1 : rb1;
    const float* W2 = isDet ? dW2 : rW2; const float* b2 = isDet ? db2 : rb2;
    const float* W3 = isDet ? dW3 : rW3; const float* b3 = isDet ? db3 : rb3;

    unsigned long long acc[8];
    run_layer2(W1, b1[tid], bufA, Wt2, acc);
    #pragma unroll
    for (int p = 0; p < 8; p++) {
        float u, v; upk2(acc[p], u, v);
        *reinterpret_cast<unsigned long long*>(&bufB[tid * TPAD + 2 * p]) =
            pk2(fmaxf(u, 0.f), fmaxf(v, 0.f));
    }
    __syncthreads();

    run_layer2(W2, b2[tid], bufB, Wt2, acc);
    #pragma unroll
    for (int p = 0; p < 8; p++) {
        float u, v; upk2(acc[p], u, v);
        *reinterpret_cast<unsigned long long*>(&bufA[tid * TPAD + 2 * p]) =
            pk2(fmaxf(u, 0.f), fmaxf(v, 0.f));
    }
    __syncthreads();

    run_layer2(W3, b3[tid], bufA, Wt2, acc);
    float* outp = isDet ? out_det : out_rec;
    const float* qp = isDet ? det_q : rec_q;
    #pragma unroll
    for (int p = 0; p < 8; p++) {
        float u, v; upk2(acc[p], u, v);
        int g0 = blk * GTOK + 2 * p;
        int qi0 = g0 % kq, qi1 = (g0 + 1) % kq;
        outp[(size_t)g0 * 256 + tid]       = u + qp[qi0 * 256 + tid];
        outp[(size_t)(g0 + 1) * 256 + tid] = v + qp[qi1 * 256 + tid];
    }
}

// ---------------- launch ----------------
extern "C" void kernel_launch(void* const* d_in, const int* in_sizes, int n_in,
                              void* d_out, int out_size) {
    const float* x     = (const float*)d_in[0];
    const float* Wc    = (const float*)d_in[1];
    const float* bc    = (const float*)d_in[2];
    const float* Wb    = (const float*)d_in[3];
    const float* bb    = (const float*)d_in[4];
    const float* dW1   = (const float*)d_in[5];
    const float* db1   = (const float*)d_in[6];
    const float* dW2   = (const float*)d_in[7];
    const float* db2   = (const float*)d_in[8];
    const float* dW3   = (const float*)d_in[9];
    const float* db3   = (const float*)d_in[10];
    const float* rW1   = (const float*)d_in[11];
    const float* rb1   = (const float*)d_in[12];
    const float* rW2   = (const float*)d_in[13];
    const float* rb2   = (const float*)d_in[14];
    const float* rW3   = (const float*)d_in[15];
    const float* rb3   = (const float*)d_in[16];
    const float* det_q = (const float*)d_in[17];
    const float* rec_q = (const float*)d_in[18];
    const float* pe    = (const float*)d_in[19];

    float* out = (float*)d_out;
    float* out_det = out;               // 16*100*256 = 409600
    float* out_rec = out + 409600;      // 16*25*256  = 102400
    float* out_cls = out + 512000;      // 16*10000*2 = 320000
    float* out_bb  = out + 832000;      // 16*10000*4 = 640000

    pos_resize_kernel<<<(CDIM * NPIX + 255) / 256, 256>>>(pe);
    pos_proj_part_kernel<<<125, 320>>>(Wc, Wb);                 // 40000 threads exactly
    pos_proj_reduce_kernel<<<(6 * (NPIX / 4) + 319) / 320, 320>>>();
    main_pass_kernel<<<125, 320>>>(x, bc, bb, Wc, Wb, out_cls, out_bb); // 40000 threads, 1 wave

    cudaFuncSetAttribute(topk_kernel, cudaFuncAttributeMaxDynamicSharedMemorySize, TK_SMEM);
    topk_kernel<<<BATCH, 1024, TK_SMEM>>>();

    cudaFuncSetAttribute(mlp_kernel, cudaFuncAttributeMaxDynamicSharedMemorySize, MLP_SMEM);
    mlp_kernel<<<DET_BLOCKS + REC_BLOCKS, 256, MLP_SMEM>>>(
        x, dW1, db1, dW2, db2, dW3, db3,
        rW1, rb1, rW2, rb2, rW3, rb3,
        det_q, rec_q, out_det, out_rec);
}